// round 15
// baseline (speedup 1.0000x reference)
#include <cuda_runtime.h>
#include <cstdint>
#include <math.h>

#define BB 4
#define SS 2048
#define DD 768
#define HH 12
#define DKK 64

typedef unsigned long long ull;

static const long long OUT_ELEMS  = (long long)BB * SS * DD;
static const long long ATTN_ELEMS = (long long)BB * HH * SS * SS;

// octet permutation: logical k -> physical slot (within groups of 8)
#define PHYS8(k) (((k) & ~7) | (((k) & 3) << 1) | (((k) >> 2) & 1))

// Scratch
__device__ float g_q[BB * HH * SS * DKK];     // rounded + k-permuted
__device__ float g_k[BB * HH * SS * DKK];     // rounded + k-permuted
__device__ float g_v[BB * HH * SS * DKK];     // rounded, plain layout
__device__ float g_ctx[BB * SS * DD];         // rounded + k-permuted
__device__ float g_pre[BB * SS * DD];
__device__ float g_psum[(size_t)BB * HH * SS * 32];
__device__ float g_rowinv[(size_t)BB * HH * SS];
__device__ uint32_t g_maskbits[(size_t)BB * SS * (SS / 32)];
__device__ float g_attn_fb[(long long)BB * HH * SS * SS];
__device__ float g_wTp[4][DD * DD];           // [n][k] transposed, rounded, permuted
__device__ float g_xr[3][BB * SS * DD];       // rounded + permuted Q/K/V inputs

__device__ __forceinline__ uint32_t cvt_tf32(float x) {
    uint32_t u; asm("cvt.rna.tf32.f32 %0, %1;" : "=r"(u) : "f"(x)); return u;
}
__device__ __forceinline__ float rnd(float x) { return __uint_as_float(cvt_tf32(x)); }

__device__ __forceinline__ void mma8(float* c, const uint32_t* a, const uint32_t* b) {
    asm("mma.sync.aligned.m16n8k8.row.col.f32.tf32.tf32.f32 "
        "{%0,%1,%2,%3},{%4,%5,%6,%7},{%8,%9},{%0,%1,%2,%3};"
        : "+f"(c[0]), "+f"(c[1]), "+f"(c[2]), "+f"(c[3])
        : "r"(a[0]), "r"(a[1]), "r"(a[2]), "r"(a[3]), "r"(b[0]), "r"(b[1]));
}

__device__ __forceinline__ void cp16(uint32_t dst, const void* src) {
    asm volatile("cp.async.cg.shared.global [%0], [%1], 16;" :: "r"(dst), "l"(src));
}
__device__ __forceinline__ void cp_commit() { asm volatile("cp.async.commit_group;"); }
template<int N> __device__ __forceinline__ void cp_wait() {
    asm volatile("cp.async.wait_group %0;" :: "n"(N));
}

// ---------------------------------------------------------------------------
// Mask bit-pack: int32 [4,2048,2048] -> bitmask. bit=1 -> masked.
// ---------------------------------------------------------------------------
__global__ void __launch_bounds__(256) maskpack_kernel(const int* __restrict__ pad)
{
    size_t w = (size_t)blockIdx.x * 256 + threadIdx.x;
    const int4* p = reinterpret_cast<const int4*>(pad + w * 32);
    uint32_t bits = 0;
    #pragma unroll
    for (int t = 0; t < 8; t++) {
        int4 v = p[t];
        bits |= (uint32_t)(v.x != 0) << (4 * t);
        bits |= (uint32_t)(v.y != 0) << (4 * t + 1);
        bits |= (uint32_t)(v.z != 0) << (4 * t + 2);
        bits |= (uint32_t)(v.w != 0) << (4 * t + 3);
    }
    g_maskbits[w] = bits;
}

// ---------------------------------------------------------------------------
// Weight transpose + round + k-permute: g_wTp[z][n*DD + PHYS8(k)] = rna(W[k][n]).
// ---------------------------------------------------------------------------
__global__ void __launch_bounds__(256) wtrans_kernel(
    const float* __restrict__ Wq, const float* __restrict__ Wk,
    const float* __restrict__ Wv, const float* __restrict__ Wo)
{
    const float* W = (blockIdx.z == 0) ? Wq : (blockIdx.z == 1) ? Wk
                   : (blockIdx.z == 2) ? Wv : Wo;
    float* T = g_wTp[blockIdx.z];
    __shared__ float tile[32][33];
    int k0 = blockIdx.y * 32, n0 = blockIdx.x * 32;
    int tx = threadIdx.x & 31, ty = threadIdx.x >> 5;
    #pragma unroll
    for (int i = 0; i < 4; i++)
        tile[ty + i * 8][tx] = W[(size_t)(k0 + ty + i * 8) * DD + n0 + tx];
    __syncthreads();
    #pragma unroll
    for (int i = 0; i < 4; i++)
        T[(size_t)(n0 + ty + i * 8) * DD + k0 + PHYS8(tx)] = rnd(tile[tx][ty + i * 8]);
}

// ---------------------------------------------------------------------------
// Round + permute X inputs: one thread per octet; stores stay float4.
// ---------------------------------------------------------------------------
__global__ void __launch_bounds__(256) roundperm_kernel(
    const float* __restrict__ Q, const float* __restrict__ K, const float* __restrict__ V)
{
    const float* X = (blockIdx.y == 0) ? Q : (blockIdx.y == 1) ? K : V;
    float* O = g_xr[blockIdx.y];
    size_t o = (size_t)blockIdx.x * 256 + threadIdx.x;   // octet index
    const float4* p = reinterpret_cast<const float4*>(X) + o * 2;
    float4 lo = p[0], hi = p[1];
    float4 o0 = make_float4(rnd(lo.x), rnd(hi.x), rnd(lo.y), rnd(hi.y));
    float4 o1 = make_float4(rnd(lo.z), rnd(hi.z), rnd(lo.w), rnd(hi.w));
    float4* q = reinterpret_cast<float4*>(O) + o * 2;
    q[0] = o0; q[1] = o1;
}

// ---------------------------------------------------------------------------
// QKV projection (merged): Y = X @ W + bias, [B,H,S,DK] layout.
// 128 threads, warps 2x2, warp tile 64x32. BK=32, 2-stage, 3 CTAs/SM.
// ---------------------------------------------------------------------------
__global__ void __launch_bounds__(128, 3) qkv_kernel(
    const float* __restrict__ bq, const float* __restrict__ bk, const float* __restrict__ bv)
{
    const int z = blockIdx.z;
    const float* X = g_xr[z];
    const float* W = g_wTp[z];
    const float* bias = (z == 0) ? bq : (z == 1) ? bk : bv;
    float* Y = (z == 0) ? g_q : (z == 1) ? g_k : g_v;

    extern __shared__ float smf[];
    const uint32_t smb = (uint32_t)__cvta_generic_to_shared(smf);

    const int tid = threadIdx.x, wid = tid >> 5, lane = tid & 31;
    const int gid = lane >> 2, tig = lane & 3;
    const int m0 = blockIdx.y * 128, n0 = blockIdx.x * 64;
    const int wm = (wid >> 1) * 64, wn = (wid & 1) * 32;

    float acc[4][4][4] = {};

    #define XS(s,r,c) smf[(s)*4608 + (r)*36 + (c)]
    #define WS(s,r,c) smf[9216 + (s)*2304 + (r)*36 + (c)]   // [n][k]
    auto load_chunk = [&](int s, int k0) {
        #pragma unroll
        for (int t = 0; t < 8; t++) {
            int idx = tid + t * 128, r = idx >> 3, g = idx & 7;
            cp16(smb + (uint32_t)((s * 4608 + r * 36 + g * 4) * 4),
                 X + (size_t)(m0 + r) * DD + k0 + g * 4);
        }
        #pragma unroll
        for (int t = 0; t < 4; t++) {
            int idx = tid + t * 128, r = idx >> 3, g = idx & 7;
            cp16(smb + (uint32_t)((9216 + s * 2304 + r * 36 + g * 4) * 4),
                 W + (size_t)(n0 + r) * DD + k0 + g * 4);
        }
        cp_commit();
    };

    load_chunk(0, 0);
    for (int it = 0; it < 24; it++) {
        if (it + 1 < 24) { load_chunk((it + 1) & 1, (it + 1) * 32); cp_wait<1>(); }
        else cp_wait<0>();
        __syncthreads();
        const int s = it & 1;
        #pragma unroll
        for (int kk = 0; kk < 32; kk += 8) {
            uint32_t a[4][4], b[4][2];
            #pragma unroll
            for (int mi = 0; mi < 4; mi++) {
                int r = wm + mi * 16 + gid;
                uint2 la = *reinterpret_cast<const uint2*>(&XS(s, r, kk + 2 * tig));
                uint2 lb = *reinterpret_cast<const uint2*>(&XS(s, r + 8, kk + 2 * tig));
                a[mi][0] = la.x; a[mi][1] = lb.x; a[mi][2] = la.y; a[mi][3] = lb.y;
            }
            #pragma unroll
            for (int nj = 0; nj < 4; nj++) {
                int n = wn + nj * 8 + gid;
                uint2 w2 = *reinterpret_cast<const uint2*>(&WS(s, n, kk + 2 * tig));
                b[nj][0] = w2.x; b[nj][1] = w2.y;
            }
            #pragma unroll
            for (int mi = 0; mi < 4; mi++)
                #pragma unroll
                for (int nj = 0; nj < 4; nj++) mma8(acc[mi][nj], a[mi], b[nj]);
        }
        __syncthreads();
    }
    #undef XS
    #undef WS

    #pragma unroll
    for (int mi = 0; mi < 4; mi++)
        #pragma unroll
        for (int rr = 0; rr < 2; rr++) {
            int r = m0 + wm + mi * 16 + gid + rr * 8;
            int b_ = r >> 11, sidx = r & 2047;
            #pragma unroll
            for (int nj = 0; nj < 4; nj++) {
                int c = n0 + wn + nj * 8 + tig * 2;
                float v0 = rnd(acc[mi][nj][rr * 2 + 0] + bias[c]);
                float v1 = rnd(acc[mi][nj][rr * 2 + 1] + bias[c + 1]);
                int h = c >> 6, d = c & 63;
                float* o = Y + (((size_t)b_ * HH + h) * SS + sidx) * DKK;
                if (z == 2) {
                    *reinterpret_cast<float2*>(o + d) = make_float2(v0, v1);
                } else {
                    o[PHYS8(d)] = v0;
                    o[PHYS8(d + 1)] = v1;
                }
            }
        }
}

// ---------------------------------------------------------------------------
// Scores+exp: unchanged from R14.
// ---------------------------------------------------------------------------
__global__ void __launch_bounds__(256) scores_kernel(float* __restrict__ attn_ext)
{
    float* attn = attn_ext ? attn_ext : g_attn_fb;
    extern __shared__ uint32_t smu[];
    uint32_t (*Qs)[68] = reinterpret_cast<uint32_t(*)[68]>(smu);
    uint32_t (*Ks)[68] = reinterpret_cast<uint32_t(*)[68]>(smu + 128 * 68);
    float (*Ss)[132]   = reinterpret_cast<float(*)[132]>(smu);

    const int bh = blockIdx.z, b_ = bh / HH;
    const int q0 = blockIdx.y * 128, k0 = blockIdx.x * 128;
    const int tid = threadIdx.x, wid = tid >> 5, lane = tid & 31;
    const int gid = lane >> 2, tig = lane & 3;
    const int wm = (wid >> 1) * 32, wn = (wid & 1) * 64;

    const float* qp = g_q + ((size_t)bh * SS + q0) * DKK;
    const float* kp = g_k + ((size_t)bh * SS + k0) * DKK;

    #pragma unroll
    for (int t = 0; t < 8; t++) {
        int e = (tid + t * 256) * 4, r = e >> 6, c = e & 63;
        *reinterpret_cast<uint4*>(&Qs[r][c]) =
            *reinterpret_cast<const uint4*>(qp + (size_t)r * DKK + c);
        *reinterpret_cast<uint4*>(&Ks[r][c]) =
            *reinterpret_cast<const uint4*>(kp + (size_t)r * DKK + c);
    }
    __syncthreads();

    float acc[2][8][4] = {};
    #pragma unroll
    for (int kk = 0; kk < 64; kk += 8) {
        uint32_t a[2][4], b[8][2];
        #pragma unroll
        for (int mi = 0; mi < 2; mi++) {
            int r = wm + mi * 16 + gid;
            uint2 la = *reinterpret_cast<const uint2*>(&Qs[r][kk + 2 * tig]);
            uint2 lb = *reinterpret_cast<const uint2*>(&Qs[r + 8][kk + 2 * tig]);
            a[mi][0] = la.x; a[mi][1] = lb.x; a[mi][2] = la.y; a[mi][3] = lb.y;
        }
        #pragma unroll
        for (int nj = 0; nj < 8; nj++) {
            int n = wn + nj * 8 + gid;
            uint2 kb = *reinterpret_cast<const uint2*>(&Ks[n][kk + 2 * tig]);
            b[nj][0] = kb.x; b[nj][1] = kb.y;
        }
        #pragma unroll
        for (int mi = 0; mi < 2; mi++)
            #pragma unroll
            for (int nj = 0; nj < 8; nj++) mma8(acc[mi][nj], a[mi], b[nj]);
    }
    __syncthreads();

    #pragma unroll
    for (int mi = 0; mi < 2; mi++)
        #pragma unroll
        for (int rr = 0; rr < 2; rr++) {
            int qrl = wm + mi * 16 + gid + rr * 8;
            int qr = q0 + qrl;
            uint2 mw = *reinterpret_cast<const uint2*>(
                g_maskbits + ((size_t)b_ * SS + qr) * (SS / 32) + (k0 + wn) / 32);
            ull m64 = (ull)mw.x | ((ull)mw.y << 32);
            float rs = 0.f;
            #pragma unroll
            for (int nj = 0; nj < 8; nj++) {
                int j = nj * 8 + tig * 2;
                float v0 = acc[mi][nj][rr * 2 + 0] * 0.125f;
                float v1 = acc[mi][nj][rr * 2 + 1] * 0.125f;
                float p0 = ((m64 >> j) & 1ull) ? 0.f : __expf(v0);
                float p1 = ((m64 >> (j + 1)) & 1ull) ? 0.f : __expf(v1);
                rs += p0 + p1;
                *reinterpret_cast<float2*>(&Ss[qrl][wn + j]) = make_float2(p0, p1);
            }
            rs += __shfl_xor_sync(~0u, rs, 1);
            rs += __shfl_xor_sync(~0u, rs, 2);
            if (tig == 0)
                g_psum[((size_t)bh * SS + qr) * 32 + blockIdx.x * 2 + (wid & 1)] = rs;
        }
    __syncthreads();

    const size_t base = (size_t)bh * SS * SS;
    #pragma unroll
    for (int t = 0; t < 16; t++) {
        int idx = tid + t * 256;
        int r = idx >> 5, c4 = (idx & 31) * 4;
        float4 v = *reinterpret_cast<const float4*>(&Ss[r][c4]);
        *reinterpret_cast<float4*>(attn + base + (size_t)(q0 + r) * SS + k0 + c4) = v;
    }
}

// ---------------------------------------------------------------------------
__global__ void __launch_bounds__(256) rowinv_kernel()
{
    size_t idx = (size_t)blockIdx.x * 256 + threadIdx.x;
    const float4* p = reinterpret_cast<const float4*>(g_psum + idx * 32);
    float s = 0.f;
    #pragma unroll
    for (int t = 0; t < 8; t++) { float4 v = p[t]; s += v.x + v.y + v.z + v.w; }
    g_rowinv[idx] = 1.0f / s;
}

// ---------------------------------------------------------------------------
// Context: BK=32, 2-stage, 3 CTAs/SM. 128 threads, warps 2x2, warp tile 64x32.
// Normalize exp on load (write final attn), MMA with V (pre-rounded).
// smem floats: AS s*4608 [128][36]; VS 9216 + s*2176 [32][68]; invs @13568[128].
// ---------------------------------------------------------------------------
__global__ void __launch_bounds__(128, 3) context_kernel(float* __restrict__ attn_ext)
{
    float* attn = attn_ext ? attn_ext : g_attn_fb;
    extern __shared__ float smf[];
    const uint32_t smb = (uint32_t)__cvta_generic_to_shared(smf);
    float* invs = smf + 13568;

    const int bh = blockIdx.y, q0 = blockIdx.x * 128;
    const int tid = threadIdx.x, wid = tid >> 5, lane = tid & 31;
    const int gid = lane >> 2, tig = lane & 3;
    const int wm = (wid >> 1) * 64, wn = (wid & 1) * 32;

    float* ap = attn + ((size_t)bh * SS + q0) * SS;
    const float* vp = g_v + (size_t)bh * SS * DKK;

    invs[tid] = g_rowinv[(size_t)bh * SS + q0 + tid];

    #define AS(s,r,c) smf[(s)*4608 + (r)*36 + (c)]
    #define VS(s,r,c) smf[9216 + (s)*2176 + (r)*68 + (c)]
    auto load_chunk = [&](int s, int k0) {
        #pragma unroll
        for (int t = 0; t < 8; t++) {
            int idx = tid + t * 128, r = idx >> 3, g = idx & 7;
            cp16(smb + (uint32_t)((s * 4608 + r * 36 + g * 4) * 4),
                 ap + (size_t)r * SS + k0 + g * 4);
        }
        #pragma unroll
        for (int t = 0; t < 4; t++) {
            int idx = tid + t * 128, r = idx >> 4, g = idx & 15;
            cp16(smb + (uint32_t)((9216 + s * 2176 + r * 68 + g * 4) * 4),
                 vp + (size_t)(k0 + r) * DKK + g * 4);
        }
        cp_commit();
    };

    float acc[4][4][4] = {};
    load_chunk(0, 0);
    for (int it = 0; it < 64; it++) {
        if (it + 1 < 64) { load_chunk((it + 1) & 1, (it + 1) * 32); cp_wait<1>(); }
        else cp_wait<0>();
        __syncthreads();
        const int s = it & 1;
        const int k0 = it * 32;

        // normalize + global writeback + tf32-cvt in place (attn only)
        #pragma unroll
        for (int t = 0; t < 8; t++) {
            int idx = tid + t * 128, r = idx >> 3, c = (idx & 7) * 4;
            float4 v = *reinterpret_cast<const float4*>(&AS(s, r, c));
            float inv = invs[r];
            v.x *= inv; v.y *= inv; v.z *= inv; v.w *= inv;
            *reinterpret_cast<float4*>(ap + (size_t)r * SS + k0 + c) = v;
            uint32_t* u = reinterpret_cast<uint32_t*>(&AS(s, r, c));
            u[0] = cvt_tf32(v.x); u[1] = cvt_tf32(v.y);
            u[2] = cvt_tf32(v.z); u[3] = cvt_tf32(v.w);
        }
        __syncthreads();

        #pragma unroll
        for (int kk = 0; kk < 32; kk += 8) {
            uint32_t a[4][4], b[4][2];
            #pragma unroll
            for (int mi = 0; mi < 4; mi++) {
                int r = wm + mi * 16 + gid;
                a[mi][0] = __float_as_uint(AS(s, r, kk + tig));
                a[mi][1] = __float_as_uint(AS(s, r + 8, kk + tig));
                a[mi][2] = __float_as_uint(AS(s, r, kk + tig + 4));
                a[mi][3] = __float_as_uint(AS(s, r + 8, kk + tig + 4));
            }
            #pragma unroll
            for (int nj = 0; nj < 4; nj++) {
                int n = wn + nj * 8 + gid;
                b[nj][0] = __float_as_uint(VS(s, kk + tig, n));
                b[nj][1] = __float_as_uint(VS(s, kk + tig + 4, n));
            }
            #pragma unroll
            for (int mi = 0; mi < 4; mi++)
                #pragma unroll
                for (int nj = 0; nj < 4; nj++) mma8(acc[mi][nj], a[mi], b[nj]);
        }
        __syncthreads();
    }
    #undef AS
    #undef VS

    const int b_ = bh / HH, h = bh % HH;
    #pragma unroll
    for (int mi = 0; mi < 4; mi++)
        #pragma unroll
        for (int rr = 0; rr < 2; rr++) {
            int s = q0 + wm + mi * 16 + gid + rr * 8;
            #pragma unroll
            for (int nj = 0; nj < 4; nj++) {
                int d = wn + nj * 8 + tig * 2;
                float r0 = rnd(acc[mi][nj][rr * 2]);
                float r1 = rnd(acc[mi][nj][rr * 2 + 1]);
                float* o = &g_ctx[((size_t)b_ * SS + s) * DD + h * DKK];
                o[PHYS8(d)] = r0;
                o[PHYS8(d + 1)] = r1;
            }
        }
}

// ---------------------------------------------------------------------------
// Output projection: BK=32, 2-stage, 3 CTAs/SM. Warp tile 64x32.
// ---------------------------------------------------------------------------
__global__ void __launch_bounds__(128, 3) outproj_kernel(
    const float* __restrict__ bias, const float* __restrict__ resid)
{
    const float* X = g_ctx;
    const float* W = g_wTp[3];
    extern __shared__ float smf[];
    const uint32_t smb = (uint32_t)__cvta_generic_to_shared(smf);

    const int tid = threadIdx.x, wid = tid >> 5, lane = tid & 31;
    const int gid = lane >> 2, tig = lane & 3;
    const int m0 = blockIdx.y * 128, n0 = blockIdx.x * 64;
    const int wm = (wid >> 1) * 64, wn = (wid & 1) * 32;

    float acc[4][4][4] = {};

    #define XS(s,r,c) smf[(s)*4608 + (r)*36 + (c)]
    #define WS(s,r,c) smf[9216 + (s)*2304 + (r)*36 + (c)]
    auto load_chunk = [&](int s, int k0) {
        #pragma unroll
        for (int t = 0; t < 8; t++) {
            int idx = tid + t * 128, r = idx >> 3, g = idx & 7;
            cp16(smb + (uint32_t)((s * 4608 + r * 36 + g * 4) * 4),
                 X + (size_t)(m0 + r) * DD + k0 + g * 4);
        }
        #pragma unroll
        for (int t = 0; t < 4; t++) {
            int idx = tid + t * 128, r = idx >> 3, g = idx & 7;
            cp16(smb + (uint32_t)((9216 + s * 2304 + r * 36 + g * 4) * 4),
                 W + (size_t)(n0 + r) * DD + k0 + g * 4);
        }
        cp_commit();
    };

    load_chunk(0, 0);
    for (int it = 0; it < 24; it++) {
        if (it + 1 < 24) { load_chunk((it + 1) & 1, (it + 1) * 32); cp_wait<1>(); }
        else cp_wait<0>();
        __syncthreads();
        const int s = it & 1;
        #pragma unroll
        for (int kk = 0; kk < 32; kk += 8) {
            uint32_t a[4][4], b[4][2];
            #pragma unroll
            for (int mi = 0; mi < 4; mi++) {
                int r = wm + mi * 16 + gid;
                uint2 la = *reinterpret_cast<const uint2*>(&XS(s, r, kk + 2 * tig));
                uint2 lb = *reinterpret_cast<const uint2*>(&XS(s, r + 8, kk + 2 * tig));
                a[mi][0] = la.x; a[mi][1] = lb.x; a[mi][2] = la.y; a[mi][3] = lb.y;
            }
            #pragma unroll
            for (int nj = 0; nj < 4; nj++) {
                int n = wn + nj * 8 + gid;
                uint2 w2 = *reinterpret_cast<const uint2*>(&WS(s, n, kk + 2 * tig));
                b[nj][0] = w2.x; b[nj][1] = w2.y;
            }
            #pragma unroll
            for (int mi = 0; mi < 4; mi++)
                #pragma unroll
                for (int nj = 0; nj < 4; nj++) mma8(acc[mi][nj], a[mi], b[nj]);
        }
        __syncthreads();
    }
    #undef XS
    #undef WS

    #pragma unroll
    for (int mi = 0; mi < 4; mi++)
        #pragma unroll
        for (int rr = 0; rr < 2; rr++) {
            int r = m0 + wm + mi * 16 + gid + rr * 8;
            #pragma unroll
            for (int nj = 0; nj < 4; nj++) {
                int c = n0 + wn + nj * 8 + tig * 2;
                float v0 = acc[mi][nj][rr * 2 + 0] + bias[c];
                float v1 = acc[mi][nj][rr * 2 + 1] + bias[c + 1];
                const float2 rs = *reinterpret_cast<const float2*>(&resid[(size_t)r * DD + c]);
                *reinterpret_cast<float2*>(&g_pre[(size_t)r * DD + c]) =
                    make_float2(v0 + rs.x, v1 + rs.y);
            }
        }
}

// ---------------------------------------------------------------------------
// LayerNorm over D=768.
// ---------------------------------------------------------------------------
__global__ void __launch_bounds__(256) ln_kernel(
    const float* __restrict__ lg, const float* __restrict__ lb, float* __restrict__ out)
{
    const size_t row = blockIdx.x;
    const float* x = g_pre + row * DD;
    const int tid = threadIdx.x;
    __shared__ float red[8];

    float v[3];
    float s = 0.f;
    #pragma unroll
    for (int t = 0; t < 3; t++) { v[t] = x[tid + t * 256]; s += v[t]; }
    #pragma unroll
    for (int o = 16; o; o >>= 1) s += __shfl_xor_sync(~0u, s, o);
    if ((tid & 31) == 0) red[tid >> 5] = s;
    __syncthreads();
    s = 0.f;
    #pragma unroll
    for (int w = 0; w < 8; w++) s += red[w];
    const float mu = s * (1.0f / DD);
    __syncthreads();

    float var = 0.f;
    #pragma unroll
    for (int t = 0; t < 3; t++) { float d = v[t] - mu; var += d * d; }
    #pragma unroll
    for (int o = 16; o; o >>= 1) var += __shfl_xor_sync(~0u, var, o);
    if ((tid & 31) == 0) red[tid >> 5] = var;
    __syncthreads();
    var = 0.f;
    #pragma unroll
    for (int w = 0; w < 8; w++) var += red[w];
    const float inv = rsqrtf(var * (1.0f / DD) + 1e-5f);

    #pragma unroll
    for (int t = 0; t < 3; t++) {
        int c = tid + t * 256;
        out[row * DD + c] = (v[t] - mu) * inv * lg[c] + lb[c];
    }
}

// ---------------------------------------------------------------------------
extern "C" void kernel_launch(void* const* d_in, const int* in_sizes, int n_in,
                              void* d_out, int out_size)
{
    const float* Q  = (const float*)d_in[0];
    const float* K  = (const float*)d_in[1];
    const float* V  = (const float*)d_in[2];
    const int*   pad = (const int*)d_in[3];
    const float* Wq = (const float*)d_in[4];
    const float* bq = (const float*)d_in[5];
    const float* Wk = (const float*)d_in[6];
    const float* bk = (const float*)d_in[7];
    const float* Wv = (const float*)d_in[8];
    const float* bv = (const float*)d_in[9];
    const float* Wo = (const float*)d_in[10];
    const float* bo = (const float*)d_in[11];
    const float* lg = (const float*)d_in[12];
    const float* lb = (const float*)d_in[13];
    float* out = (float*)d_out;

    float* attn = ((long long)out_size >= OUT_ELEMS + ATTN_ELEMS) ? (out + OUT_ELEMS)
                                                                  : nullptr;

    const int GEMM_SMEM   = 13824 * 4;   // 55296
    const int SCORES_SMEM = 17408 * 4;   // 69632
    const int CTX_SMEM    = 13696 * 4;   // 54784
    cudaFuncSetAttribute(qkv_kernel, cudaFuncAttributeMaxDynamicSharedMemorySize, GEMM_SMEM);
    cudaFuncSetAttribute(outproj_kernel, cudaFuncAttributeMaxDynamicSharedMemorySize, GEMM_SMEM);
    cudaFuncSetAttribute(scores_kernel, cudaFuncAttributeMaxDynamicSharedMemorySize, SCORES_SMEM);
    cudaFuncSetAttribute(context_kernel, cudaFuncAttributeMaxDynamicSharedMemorySize, CTX_SMEM);

    maskpack_kernel<<<(BB * SS * (SS / 32)) / 256, 256>>>(pad);
    wtrans_kernel<<<dim3(24, 24, 4), 256>>>(Wq, Wk, Wv, Wo);
    roundperm_kernel<<<dim3((BB * SS * DD / 8) / 256, 3), 256>>>(Q, K, V);

    dim3 gq(DD / 64, (BB * SS) / 128, 3);       // (12, 64, 3)
    qkv_kernel<<<gq, 128, GEMM_SMEM>>>(bq, bk, bv);

    dim3 gs(SS / 128, SS / 128, BB * HH);       // (16, 16, 48)
    scores_kernel<<<gs, 256, SCORES_SMEM>>>(attn);

    rowinv_kernel<<<(BB * HH * SS) / 256, 256>>>();

    dim3 gc(SS / 128, BB * HH);                 // (16, 48)
    context_kernel<<<gc, 128, CTX_SMEM>>>(attn);

    dim3 gp(DD / 64, (BB * SS) / 128);          // (12, 64)
    outproj_kernel<<<gp, 128, GEMM_SMEM>>>(bo, Q);

    ln_kernel<<<BB * SS, 256>>>(lg, lb, out);
}

// round 17
// speedup vs baseline: 1.5006x; 1.5006x over previous
#include <cuda_runtime.h>
#include <cstdint>
#include <math.h>

#define BB 4
#define SS 2048
#define DD 768
#define HH 12
#define DKK 64

typedef unsigned long long ull;

static const long long OUT_ELEMS  = (long long)BB * SS * DD;
static const long long ATTN_ELEMS = (long long)BB * HH * SS * SS;

// octet permutation: logical k -> physical slot (within groups of 8)
#define PHYS8(k) (((k) & ~7) | (((k) & 3) << 1) | (((k) >> 2) & 1))

// Scratch
__device__ float g_q[BB * HH * SS * DKK];     // rounded + k-permuted
__device__ float g_k[BB * HH * SS * DKK];     // rounded + k-permuted
__device__ float g_v[BB * HH * SS * DKK];     // rounded, plain layout
__device__ float g_ctx[BB * SS * DD];         // rounded + k-permuted
__device__ float g_pre[BB * SS * DD];
__device__ float g_psum[(size_t)BB * HH * SS * 32];
__device__ float g_rowinv[(size_t)BB * HH * SS];
__device__ uint32_t g_maskbits[(size_t)BB * SS * (SS / 32)];
__device__ float g_attn_fb[(long long)BB * HH * SS * SS];
__device__ float g_wTp[4][DD * DD];           // [n][k] transposed, rounded, permuted
__device__ float g_xr[3][BB * SS * DD];       // rounded + permuted Q/K/V inputs

__device__ __forceinline__ uint32_t cvt_tf32(float x) {
    uint32_t u; asm("cvt.rna.tf32.f32 %0, %1;" : "=r"(u) : "f"(x)); return u;
}
__device__ __forceinline__ float rnd(float x) { return __uint_as_float(cvt_tf32(x)); }

__device__ __forceinline__ void mma8(float* c, const uint32_t* a, const uint32_t* b) {
    asm("mma.sync.aligned.m16n8k8.row.col.f32.tf32.tf32.f32 "
        "{%0,%1,%2,%3},{%4,%5,%6,%7},{%8,%9},{%0,%1,%2,%3};"
        : "+f"(c[0]), "+f"(c[1]), "+f"(c[2]), "+f"(c[3])
        : "r"(a[0]), "r"(a[1]), "r"(a[2]), "r"(a[3]), "r"(b[0]), "r"(b[1]));
}

__device__ __forceinline__ void cp16(uint32_t dst, const void* src) {
    asm volatile("cp.async.cg.shared.global [%0], [%1], 16;" :: "r"(dst), "l"(src));
}
__device__ __forceinline__ void cp_commit() { asm volatile("cp.async.commit_group;"); }
template<int N> __device__ __forceinline__ void cp_wait() {
    asm volatile("cp.async.wait_group %0;" :: "n"(N));
}

// ---------------------------------------------------------------------------
// Mask bit-pack: int32 [4,2048,2048] -> bitmask. bit=1 -> masked.
// ---------------------------------------------------------------------------
__global__ void __launch_bounds__(256) maskpack_kernel(const int* __restrict__ pad)
{
    size_t w = (size_t)blockIdx.x * 256 + threadIdx.x;
    const int4* p = reinterpret_cast<const int4*>(pad + w * 32);
    uint32_t bits = 0;
    #pragma unroll
    for (int t = 0; t < 8; t++) {
        int4 v = p[t];
        bits |= (uint32_t)(v.x != 0) << (4 * t);
        bits |= (uint32_t)(v.y != 0) << (4 * t + 1);
        bits |= (uint32_t)(v.z != 0) << (4 * t + 2);
        bits |= (uint32_t)(v.w != 0) << (4 * t + 3);
    }
    g_maskbits[w] = bits;
}

// ---------------------------------------------------------------------------
// Weight transpose + round + k-permute: g_wTp[z][n*DD + PHYS8(k)] = rna(W[k][n]).
// ---------------------------------------------------------------------------
__global__ void __launch_bounds__(256) wtrans_kernel(
    const float* __restrict__ Wq, const float* __restrict__ Wk,
    const float* __restrict__ Wv, const float* __restrict__ Wo)
{
    const float* W = (blockIdx.z == 0) ? Wq : (blockIdx.z == 1) ? Wk
                   : (blockIdx.z == 2) ? Wv : Wo;
    float* T = g_wTp[blockIdx.z];
    __shared__ float tile[32][33];
    int k0 = blockIdx.y * 32, n0 = blockIdx.x * 32;
    int tx = threadIdx.x & 31, ty = threadIdx.x >> 5;
    #pragma unroll
    for (int i = 0; i < 4; i++)
        tile[ty + i * 8][tx] = W[(size_t)(k0 + ty + i * 8) * DD + n0 + tx];
    __syncthreads();
    #pragma unroll
    for (int i = 0; i < 4; i++)
        T[(size_t)(n0 + ty + i * 8) * DD + k0 + PHYS8(tx)] = rnd(tile[tx][ty + i * 8]);
}

// ---------------------------------------------------------------------------
// Round + permute X inputs: one thread per octet; stores stay float4.
// ---------------------------------------------------------------------------
__global__ void __launch_bounds__(256) roundperm_kernel(
    const float* __restrict__ Q, const float* __restrict__ K, const float* __restrict__ V)
{
    const float* X = (blockIdx.y == 0) ? Q : (blockIdx.y == 1) ? K : V;
    float* O = g_xr[blockIdx.y];
    size_t o = (size_t)blockIdx.x * 256 + threadIdx.x;   // octet index
    const float4* p = reinterpret_cast<const float4*>(X) + o * 2;
    float4 lo = p[0], hi = p[1];
    float4 o0 = make_float4(rnd(lo.x), rnd(hi.x), rnd(lo.y), rnd(hi.y));
    float4 o1 = make_float4(rnd(lo.z), rnd(hi.z), rnd(lo.w), rnd(hi.w));
    float4* q = reinterpret_cast<float4*>(O) + o * 2;
    q[0] = o0; q[1] = o1;
}

// ---------------------------------------------------------------------------
// QKV projection (merged): Y = X @ W + bias, [B,H,S,DK] layout.
// 128 threads, warps 2x2, warp tile 64x32. BK=32, 2-stage, 3 CTAs/SM.
// ---------------------------------------------------------------------------
__global__ void __launch_bounds__(128, 3) qkv_kernel(
    const float* __restrict__ bq, const float* __restrict__ bk, const float* __restrict__ bv)
{
    const int z = blockIdx.z;
    const float* X = g_xr[z];
    const float* W = g_wTp[z];
    const float* bias = (z == 0) ? bq : (z == 1) ? bk : bv;
    float* Y = (z == 0) ? g_q : (z == 1) ? g_k : g_v;

    extern __shared__ float smf[];
    const uint32_t smb = (uint32_t)__cvta_generic_to_shared(smf);

    const int tid = threadIdx.x, wid = tid >> 5, lane = tid & 31;
    const int gid = lane >> 2, tig = lane & 3;
    const int m0 = blockIdx.y * 128, n0 = blockIdx.x * 64;
    const int wm = (wid >> 1) * 64, wn = (wid & 1) * 32;

    float acc[4][4][4] = {};

    #define XS(s,r,c) smf[(s)*4608 + (r)*36 + (c)]
    #define WS(s,r,c) smf[9216 + (s)*2304 + (r)*36 + (c)]   // [n][k]
    auto load_chunk = [&](int s, int k0) {
        #pragma unroll
        for (int t = 0; t < 8; t++) {
            int idx = tid + t * 128, r = idx >> 3, g = idx & 7;
            cp16(smb + (uint32_t)((s * 4608 + r * 36 + g * 4) * 4),
                 X + (size_t)(m0 + r) * DD + k0 + g * 4);
        }
        #pragma unroll
        for (int t = 0; t < 4; t++) {
            int idx = tid + t * 128, r = idx >> 3, g = idx & 7;
            cp16(smb + (uint32_t)((9216 + s * 2304 + r * 36 + g * 4) * 4),
                 W + (size_t)(n0 + r) * DD + k0 + g * 4);
        }
        cp_commit();
    };

    load_chunk(0, 0);
    for (int it = 0; it < 24; it++) {
        if (it + 1 < 24) { load_chunk((it + 1) & 1, (it + 1) * 32); cp_wait<1>(); }
        else cp_wait<0>();
        __syncthreads();
        const int s = it & 1;
        #pragma unroll
        for (int kk = 0; kk < 32; kk += 8) {
            uint32_t a[4][4], b[4][2];
            #pragma unroll
            for (int mi = 0; mi < 4; mi++) {
                int r = wm + mi * 16 + gid;
                uint2 la = *reinterpret_cast<const uint2*>(&XS(s, r, kk + 2 * tig));
                uint2 lb = *reinterpret_cast<const uint2*>(&XS(s, r + 8, kk + 2 * tig));
                a[mi][0] = la.x; a[mi][1] = lb.x; a[mi][2] = la.y; a[mi][3] = lb.y;
            }
            #pragma unroll
            for (int nj = 0; nj < 4; nj++) {
                int n = wn + nj * 8 + gid;
                uint2 w2 = *reinterpret_cast<const uint2*>(&WS(s, n, kk + 2 * tig));
                b[nj][0] = w2.x; b[nj][1] = w2.y;
            }
            #pragma unroll
            for (int mi = 0; mi < 4; mi++)
                #pragma unroll
                for (int nj = 0; nj < 4; nj++) mma8(acc[mi][nj], a[mi], b[nj]);
        }
        __syncthreads();
    }
    #undef XS
    #undef WS

    #pragma unroll
    for (int mi = 0; mi < 4; mi++)
        #pragma unroll
        for (int rr = 0; rr < 2; rr++) {
            int r = m0 + wm + mi * 16 + gid + rr * 8;
            int b_ = r >> 11, sidx = r & 2047;
            #pragma unroll
            for (int nj = 0; nj < 4; nj++) {
                int c = n0 + wn + nj * 8 + tig * 2;
                float v0 = rnd(acc[mi][nj][rr * 2 + 0] + bias[c]);
                float v1 = rnd(acc[mi][nj][rr * 2 + 1] + bias[c + 1]);
                int h = c >> 6, d = c & 63;
                float* o = Y + (((size_t)b_ * HH + h) * SS + sidx) * DKK;
                if (z == 2) {
                    *reinterpret_cast<float2*>(o + d) = make_float2(v0, v1);
                } else {
                    o[PHYS8(d)] = v0;
                    o[PHYS8(d + 1)] = v1;
                }
            }
        }
}

// ---------------------------------------------------------------------------
// Scores+exp: q/k pre-rounded + permuted -> raw uint4 staging, LDS.64 frags.
// ---------------------------------------------------------------------------
__global__ void __launch_bounds__(256) scores_kernel(float* __restrict__ attn_ext)
{
    float* attn = attn_ext ? attn_ext : g_attn_fb;
    extern __shared__ uint32_t smu[];
    uint32_t (*Qs)[68] = reinterpret_cast<uint32_t(*)[68]>(smu);
    uint32_t (*Ks)[68] = reinterpret_cast<uint32_t(*)[68]>(smu + 128 * 68);
    float (*Ss)[132]   = reinterpret_cast<float(*)[132]>(smu);

    const int bh = blockIdx.z, b_ = bh / HH;
    const int q0 = blockIdx.y * 128, k0 = blockIdx.x * 128;
    const int tid = threadIdx.x, wid = tid >> 5, lane = tid & 31;
    const int gid = lane >> 2, tig = lane & 3;
    const int wm = (wid >> 1) * 32, wn = (wid & 1) * 64;

    const float* qp = g_q + ((size_t)bh * SS + q0) * DKK;
    const float* kp = g_k + ((size_t)bh * SS + k0) * DKK;

    #pragma unroll
    for (int t = 0; t < 8; t++) {
        int e = (tid + t * 256) * 4, r = e >> 6, c = e & 63;
        *reinterpret_cast<uint4*>(&Qs[r][c]) =
            *reinterpret_cast<const uint4*>(qp + (size_t)r * DKK + c);
        *reinterpret_cast<uint4*>(&Ks[r][c]) =
            *reinterpret_cast<const uint4*>(kp + (size_t)r * DKK + c);
    }
    __syncthreads();

    float acc[2][8][4] = {};
    #pragma unroll
    for (int kk = 0; kk < 64; kk += 8) {
        uint32_t a[2][4], b[8][2];
        #pragma unroll
        for (int mi = 0; mi < 2; mi++) {
            int r = wm + mi * 16 + gid;
            uint2 la = *reinterpret_cast<const uint2*>(&Qs[r][kk + 2 * tig]);
            uint2 lb = *reinterpret_cast<const uint2*>(&Qs[r + 8][kk + 2 * tig]);
            a[mi][0] = la.x; a[mi][1] = lb.x; a[mi][2] = la.y; a[mi][3] = lb.y;
        }
        #pragma unroll
        for (int nj = 0; nj < 8; nj++) {
            int n = wn + nj * 8 + gid;
            uint2 kb = *reinterpret_cast<const uint2*>(&Ks[n][kk + 2 * tig]);
            b[nj][0] = kb.x; b[nj][1] = kb.y;
        }
        #pragma unroll
        for (int mi = 0; mi < 2; mi++)
            #pragma unroll
            for (int nj = 0; nj < 8; nj++) mma8(acc[mi][nj], a[mi], b[nj]);
    }
    __syncthreads();

    #pragma unroll
    for (int mi = 0; mi < 2; mi++)
        #pragma unroll
        for (int rr = 0; rr < 2; rr++) {
            int qrl = wm + mi * 16 + gid + rr * 8;
            int qr = q0 + qrl;
            uint2 mw = *reinterpret_cast<const uint2*>(
                g_maskbits + ((size_t)b_ * SS + qr) * (SS / 32) + (k0 + wn) / 32);
            ull m64 = (ull)mw.x | ((ull)mw.y << 32);
            float rs = 0.f;
            #pragma unroll
            for (int nj = 0; nj < 8; nj++) {
                int j = nj * 8 + tig * 2;
                float v0 = acc[mi][nj][rr * 2 + 0] * 0.125f;
                float v1 = acc[mi][nj][rr * 2 + 1] * 0.125f;
                float p0 = ((m64 >> j) & 1ull) ? 0.f : __expf(v0);
                float p1 = ((m64 >> (j + 1)) & 1ull) ? 0.f : __expf(v1);
                rs += p0 + p1;
                *reinterpret_cast<float2*>(&Ss[qrl][wn + j]) = make_float2(p0, p1);
            }
            rs += __shfl_xor_sync(~0u, rs, 1);
            rs += __shfl_xor_sync(~0u, rs, 2);
            if (tig == 0)
                g_psum[((size_t)bh * SS + qr) * 32 + blockIdx.x * 2 + (wid & 1)] = rs;
        }
    __syncthreads();

    const size_t base = (size_t)bh * SS * SS;
    #pragma unroll
    for (int t = 0; t < 16; t++) {
        int idx = tid + t * 256;
        int r = idx >> 5, c4 = (idx & 31) * 4;
        float4 v = *reinterpret_cast<const float4*>(&Ss[r][c4]);
        *reinterpret_cast<float4*>(attn + base + (size_t)(q0 + r) * SS + k0 + c4) = v;
    }
}

// ---------------------------------------------------------------------------
__global__ void __launch_bounds__(256) rowinv_kernel()
{
    size_t idx = (size_t)blockIdx.x * 256 + threadIdx.x;
    const float4* p = reinterpret_cast<const float4*>(g_psum + idx * 32);
    float s = 0.f;
    #pragma unroll
    for (int t = 0; t < 8; t++) { float4 v = p[t]; s += v.x + v.y + v.z + v.w; }
    g_rowinv[idx] = 1.0f / s;
}

// ---------------------------------------------------------------------------
// Context: BK=64, 2-stage (R14 config). 128 threads, warps 2x2, warp tile 64x32.
// Normalize exp on load (write final attn), MMA with V (pre-rounded).
// ---------------------------------------------------------------------------
__global__ void __launch_bounds__(128) context_kernel(float* __restrict__ attn_ext)
{
    float* attn = attn_ext ? attn_ext : g_attn_fb;
    extern __shared__ float smf[];
    const uint32_t smb = (uint32_t)__cvta_generic_to_shared(smf);
    float* invs = smf + 26112;

    const int bh = blockIdx.y, q0 = blockIdx.x * 128;
    const int tid = threadIdx.x, wid = tid >> 5, lane = tid & 31;
    const int gid = lane >> 2, tig = lane & 3;
    const int wm = (wid >> 1) * 64, wn = (wid & 1) * 32;

    float* ap = attn + ((size_t)bh * SS + q0) * SS;
    const float* vp = g_v + (size_t)bh * SS * DKK;

    invs[tid] = g_rowinv[(size_t)bh * SS + q0 + tid];

    #define AS(s,r,c) smf[(s)*8704 + (r)*68 + (c)]
    #define VS(s,r,c) smf[17408 + (s)*4352 + (r)*68 + (c)]
    auto load_chunk = [&](int s, int k0) {
        #pragma unroll
        for (int t = 0; t < 16; t++) {
            int e = (tid + t * 128) * 4, r = e >> 6, c = e & 63;
            cp16(smb + (uint32_t)((s * 8704 + r * 68 + c) * 4),
                 ap + (size_t)r * SS + k0 + c);
        }
        #pragma unroll
        for (int t = 0; t < 8; t++) {
            int e = (tid + t * 128) * 4, r = e >> 6, c = e & 63;
            cp16(smb + (uint32_t)((17408 + s * 4352 + r * 68 + c) * 4),
                 vp + (size_t)(k0 + r) * DKK + c);
        }
        cp_commit();
    };

    float acc[4][4][4] = {};
    load_chunk(0, 0);
    for (int it = 0; it < 32; it++) {
        if (it + 1 < 32) { load_chunk((it + 1) & 1, (it + 1) * 64); cp_wait<1>(); }
        else cp_wait<0>();
        __syncthreads();
        const int s = it & 1;
        const int k0 = it * 64;

        // normalize + global writeback + tf32-cvt in place (attn only)
        #pragma unroll
        for (int t = 0; t < 16; t++) {
            int e = (tid + t * 128) * 4, r = e >> 6, c = e & 63;
            float4 v = *reinterpret_cast<const float4*>(&AS(s, r, c));
            float inv = invs[r];
            v.x *= inv; v.y *= inv; v.z *= inv; v.w *= inv;
            *reinterpret_cast<float4*>(ap + (size_t)r * SS + k0 + c) = v;
            uint32_t* u = reinterpret_cast<uint32_t*>(&AS(s, r, c));
            u[0] = cvt_tf32(v.x); u[1] = cvt_tf32(v.y);
            u[2] = cvt_tf32(v.z); u[3] = cvt_tf32(v.w);
        }
        __syncthreads();

        #pragma unroll
        for (int kk = 0; kk < 64; kk += 8) {
            uint32_t a[4][4], b[4][2];
            #pragma unroll
            for (int mi = 0; mi < 4; mi++) {
                int r = wm + mi * 16 + gid;
                a[mi][0] = __float_as_uint(AS(s, r, kk + tig));
                a[mi][1] = __float_as_uint(AS(s, r + 8, kk + tig));
                a[mi][2] = __float_as_uint(AS(s, r, kk + tig + 4));
                a[mi][3] = __float_as_uint(AS(s, r + 8, kk + tig + 4));
            }
            #pragma unroll
            for (int nj = 0; nj < 4; nj++) {
                int n = wn + nj * 8 + gid;
                b[nj][0] = __float_as_uint(VS(s, kk + tig, n));
                b[nj][1] = __float_as_uint(VS(s, kk + tig + 4, n));
            }
            #pragma unroll
            for (int mi = 0; mi < 4; mi++)
                #pragma unroll
                for (int nj = 0; nj < 4; nj++) mma8(acc[mi][nj], a[mi], b[nj]);
        }
        __syncthreads();
    }
    #undef AS
    #undef VS

    const int b_ = bh / HH, h = bh % HH;
    #pragma unroll
    for (int mi = 0; mi < 4; mi++)
        #pragma unroll
        for (int rr = 0; rr < 2; rr++) {
            int s = q0 + wm + mi * 16 + gid + rr * 8;
            #pragma unroll
            for (int nj = 0; nj < 4; nj++) {
                int d = wn + nj * 8 + tig * 2;
                float r0 = rnd(acc[mi][nj][rr * 2]);
                float r1 = rnd(acc[mi][nj][rr * 2 + 1]);
                float* o = &g_ctx[((size_t)b_ * SS + s) * DD + h * DKK];
                o[PHYS8(d)] = r0;
                o[PHYS8(d + 1)] = r1;
            }
        }
}

// ---------------------------------------------------------------------------
// Output projection: BK=32, 2-stage, 3 CTAs/SM. Warp tile 64x32.
// ---------------------------------------------------------------------------
__global__ void __launch_bounds__(128, 3) outproj_kernel(
    const float* __restrict__ bias, const float* __restrict__ resid)
{
    const float* X = g_ctx;
    const float* W = g_wTp[3];
    extern __shared__ float smf[];
    const uint32_t smb = (uint32_t)__cvta_generic_to_shared(smf);

    const int tid = threadIdx.x, wid = tid >> 5, lane = tid & 31;
    const int gid = lane >> 2, tig = lane & 3;
    const int m0 = blockIdx.y * 128, n0 = blockIdx.x * 64;
    const int wm = (wid >> 1) * 64, wn = (wid & 1) * 32;

    float acc[4][4][4] = {};

    #define XS(s,r,c) smf[(s)*4608 + (r)*36 + (c)]
    #define WS(s,r,c) smf[9216 + (s)*2304 + (r)*36 + (c)]
    auto load_chunk = [&](int s, int k0) {
        #pragma unroll
        for (int t = 0; t < 8; t++) {
            int idx = tid + t * 128, r = idx >> 3, g = idx & 7;
            cp16(smb + (uint32_t)((s * 4608 + r * 36 + g * 4) * 4),
                 X + (size_t)(m0 + r) * DD + k0 + g * 4);
        }
        #pragma unroll
        for (int t = 0; t < 4; t++) {
            int idx = tid + t * 128, r = idx >> 3, g = idx & 7;
            cp16(smb + (uint32_t)((9216 + s * 2304 + r * 36 + g * 4) * 4),
                 W + (size_t)(n0 + r) * DD + k0 + g * 4);
        }
        cp_commit();
    };

    load_chunk(0, 0);
    for (int it = 0; it < 24; it++) {
        if (it + 1 < 24) { load_chunk((it + 1) & 1, (it + 1) * 32); cp_wait<1>(); }
        else cp_wait<0>();
        __syncthreads();
        const int s = it & 1;
        #pragma unroll
        for (int kk = 0; kk < 32; kk += 8) {
            uint32_t a[4][4], b[4][2];
            #pragma unroll
            for (int mi = 0; mi < 4; mi++) {
                int r = wm + mi * 16 + gid;
                uint2 la = *reinterpret_cast<const uint2*>(&XS(s, r, kk + 2 * tig));
                uint2 lb = *reinterpret_cast<const uint2*>(&XS(s, r + 8, kk + 2 * tig));
                a[mi][0] = la.x; a[mi][1] = lb.x; a[mi][2] = la.y; a[mi][3] = lb.y;
            }
            #pragma unroll
            for (int nj = 0; nj < 4; nj++) {
                int n = wn + nj * 8 + gid;
                uint2 w2 = *reinterpret_cast<const uint2*>(&WS(s, n, kk + 2 * tig));
                b[nj][0] = w2.x; b[nj][1] = w2.y;
            }
            #pragma unroll
            for (int mi = 0; mi < 4; mi++)
                #pragma unroll
                for (int nj = 0; nj < 4; nj++) mma8(acc[mi][nj], a[mi], b[nj]);
        }
        __syncthreads();
    }
    #undef XS
    #undef WS

    #pragma unroll
    for (int mi = 0; mi < 4; mi++)
        #pragma unroll
        for (int rr = 0; rr < 2; rr++) {
            int r = m0 + wm + mi * 16 + gid + rr * 8;
            #pragma unroll
            for (int nj = 0; nj < 4; nj++) {
                int c = n0 + wn + nj * 8 + tig * 2;
                float v0 = acc[mi][nj][rr * 2 + 0] + bias[c];
                float v1 = acc[mi][nj][rr * 2 + 1] + bias[c + 1];
                const float2 rs = *reinterpret_cast<const float2*>(&resid[(size_t)r * DD + c]);
                *reinterpret_cast<float2*>(&g_pre[(size_t)r * DD + c]) =
                    make_float2(v0 + rs.x, v1 + rs.y);
            }
        }
}

// ---------------------------------------------------------------------------
// LayerNorm over D=768.
// ---------------------------------------------------------------------------
__global__ void __launch_bounds__(256) ln_kernel(
    const float* __restrict__ lg, const float* __restrict__ lb, float* __restrict__ out)
{
    const size_t row = blockIdx.x;
    const float* x = g_pre + row * DD;
    const int tid = threadIdx.x;
    __shared__ float red[8];

    float v[3];
    float s = 0.f;
    #pragma unroll
    for (int t = 0; t < 3; t++) { v[t] = x[tid + t * 256]; s += v[t]; }
    #pragma unroll
    for (int o = 16; o; o >>= 1) s += __shfl_xor_sync(~0u, s, o);
    if ((tid & 31) == 0) red[tid >> 5] = s;
    __syncthreads();
    s = 0.f;
    #pragma unroll
    for (int w = 0; w < 8; w++) s += red[w];
    const float mu = s * (1.0f / DD);
    __syncthreads();

    float var = 0.f;
    #pragma unroll
    for (int t = 0; t < 3; t++) { float d = v[t] - mu; var += d * d; }
    #pragma unroll
    for (int o = 16; o; o >>= 1) var += __shfl_xor_sync(~0u, var, o);
    if ((tid & 31) == 0) red[tid >> 5] = var;
    __syncthreads();
    var = 0.f;
    #pragma unroll
    for (int w = 0; w < 8; w++) var += red[w];
    const float inv = rsqrtf(var * (1.0f / DD) + 1e-5f);

    #pragma unroll
    for (int t = 0; t < 3; t++) {
        int c = tid + t * 256;
        out[row * DD + c] = (v[t] - mu) * inv * lg[c] + lb[c];
    }
}

// ---------------------------------------------------------------------------
extern "C" void kernel_launch(void* const* d_in, const int* in_sizes, int n_in,
                              void* d_out, int out_size)
{
    const float* Q  = (const float*)d_in[0];
    const float* K  = (const float*)d_in[1];
    const float* V  = (const float*)d_in[2];
    const int*   pad = (const int*)d_in[3];
    const float* Wq = (const float*)d_in[4];
    const float* bq = (const float*)d_in[5];
    const float* Wk = (const float*)d_in[6];
    const float* bk = (const float*)d_in[7];
    const float* Wv = (const float*)d_in[8];
    const float* bv = (const float*)d_in[9];
    const float* Wo = (const float*)d_in[10];
    const float* bo = (const float*)d_in[11];
    const float* lg = (const float*)d_in[12];
    const float* lb = (const float*)d_in[13];
    float* out = (float*)d_out;

    float* attn = ((long long)out_size >= OUT_ELEMS + ATTN_ELEMS) ? (out + OUT_ELEMS)
                                                                  : nullptr;

    const int GEMM_SMEM   = 13824 * 4;   // 55296
    const int SCORES_SMEM = 17408 * 4;   // 69632
    const int CTX_SMEM    = 26240 * 4;   // 104960
    cudaFuncSetAttribute(qkv_kernel, cudaFuncAttributeMaxDynamicSharedMemorySize, GEMM_SMEM);
    cudaFuncSetAttribute(outproj_kernel, cudaFuncAttributeMaxDynamicSharedMemorySize, GEMM_SMEM);
    cudaFuncSetAttribute(scores_kernel, cudaFuncAttributeMaxDynamicSharedMemorySize, SCORES_SMEM);
    cudaFuncSetAttribute(context_kernel, cudaFuncAttributeMaxDynamicSharedMemorySize, CTX_SMEM);

    maskpack_kernel<<<(BB * SS * (SS / 32)) / 256, 256>>>(pad);
    wtrans_kernel<<<dim3(24, 24, 4), 256>>>(Wq, Wk, Wv, Wo);
    roundperm_kernel<<<dim3((BB * SS * DD / 8) / 256, 3), 256>>>(Q, K, V);

    dim3 gq(DD / 64, (BB * SS) / 128, 3);       // (12, 64, 3)
    qkv_kernel<<<gq, 128, GEMM_SMEM>>>(bq, bk, bv);

    dim3 gs(SS / 128, SS / 128, BB * HH);       // (16, 16, 48)
    scores_kernel<<<gs, 256, SCORES_SMEM>>>(attn);

    rowinv_kernel<<<(BB * HH * SS) / 256, 256>>>();

    dim3 gc(SS / 128, BB * HH);                 // (16, 48)
    context_kernel<<<gc, 128, CTX_SMEM>>>(attn);

    dim3 gp(DD / 64, (BB * SS) / 128);          // (12, 64)
    outproj_kernel<<<gp, 128, GEMM_SMEM>>>(bo, Q);

    ln_kernel<<<BB * SS, 256>>>(lg, lb, out);
}